// round 10
// baseline (speedup 1.0000x reference)
#include <cuda_runtime.h>
#include <cstdint>

typedef unsigned long long u64;

#define B_SZ 256
#define T_SZ 8192
#define PAIRS 2
#define NTHR 256
#define ELEMS_PER_BLOCK (NTHR * PAIRS * 2)   // 1024
#define SQRT7 2.6457513110645906f

// Per-batch folded style constants (mid-layer scales pre-multiplied by sqrt(7)):
// [0:8) p1  [8:16) q1  [16:24) bias1
// [24:32) scale2' [32:40) bias2 ... [56:64) scale4' [64:72) bias4
__device__ float g_style[B_SZ * 72];

// Grid-uniform transformed weights (centered, 0.505-prescaled, f32x2-dup'd).
struct CW {
    u64 w2[64], w3[64], w4[64];
    u64 b2[8],  b3[8],  b4[8];
    u64 w5[8];
    u64 A, B, C, b5;
};
__device__ CW g_cw;
__constant__ CW c_cw;

// ---------------- packed f32x2 helpers ----------------
__device__ __forceinline__ u64 pk2(float lo, float hi) {
    u64 r;
    asm("mov.b64 %0, {%1, %2};" : "=l"(r)
        : "r"(__float_as_uint(lo)), "r"(__float_as_uint(hi)));
    return r;
}
__device__ __forceinline__ void up2(u64 v, float& lo, float& hi) {
    unsigned a, b;
    asm("mov.b64 {%0, %1}, %2;" : "=r"(a), "=r"(b) : "l"(v));
    lo = __uint_as_float(a); hi = __uint_as_float(b);
}
__device__ __forceinline__ u64 dup2(float v) { return pk2(v, v); }
__device__ __forceinline__ u64 fma2(u64 a, u64 b, u64 c) {
    u64 d; asm("fma.rn.f32x2 %0, %1, %2, %3;" : "=l"(d) : "l"(a), "l"(b), "l"(c));
    return d;
}
__device__ __forceinline__ u64 mul2(u64 a, u64 b) {
    u64 d; asm("mul.rn.f32x2 %0, %1, %2;" : "=l"(d) : "l"(a), "l"(b));
    return d;
}
__device__ __forceinline__ u64 add2(u64 a, u64 b) {
    u64 d; asm("add.rn.f32x2 %0, %1, %2;" : "=l"(d) : "l"(a), "l"(b));
    return d;
}
__device__ __forceinline__ void lds2(const u64* p, u64& a, u64& b) {
    asm("ld.shared.v2.u64 {%0, %1}, [%2];"
        : "=l"(a), "=l"(b) : "l"(__cvta_generic_to_shared(p)));
}
__device__ __forceinline__ float rsqrt_ap(float v) {
    float r; asm("rsqrt.approx.f32 %0, %1;" : "=f"(r) : "f"(v));
    return r;
}

// folded lrelu feeding a 0.505-prescaled next layer
#define C98 0.980198019801980198f
__device__ __forceinline__ u64 lrelu2f(u64 v, u64 c98) {
    u64 a = v & 0x7fffffff7fffffffULL;
    return fma2(c98, a, v);
}
// full lrelu (output only)
__device__ __forceinline__ u64 lrelu2(u64 v, u64 c505, u64 c495) {
    u64 a = v & 0x7fffffff7fffffffULL;
    return fma2(c495, a, mul2(c505, v));
}

// ---------------- tiny weight-transform kernel (1 block) --------------------
__global__ void wtrans_k(const float* __restrict__ w1, const float* __restrict__ b1,
                         const float* __restrict__ w2, const float* __restrict__ b2,
                         const float* __restrict__ w3, const float* __restrict__ b3,
                         const float* __restrict__ w4, const float* __restrict__ b4,
                         const float* __restrict__ w5, const float* __restrict__ b5)
{
    int t = threadIdx.x;
    if (t < 64) {
        float v2 = w2[t], v3 = w3[t], v4 = w4[t];
        float m2 = v2, m3 = v3, m4 = v4;
        #pragma unroll
        for (int d = 1; d < 8; d <<= 1) {
            m2 += __shfl_xor_sync(0xffffffffu, m2, d);
            m3 += __shfl_xor_sync(0xffffffffu, m3, d);
            m4 += __shfl_xor_sync(0xffffffffu, m4, d);
        }
        g_cw.w2[t] = dup2(0.505f * (v2 - m2 * 0.125f));
        g_cw.w3[t] = dup2(0.505f * (v3 - m3 * 0.125f));
        g_cw.w4[t] = dup2(0.505f * (v4 - m4 * 0.125f));
    }
    if (t >= 64 && t < 72) {
        int j = t - 64;
        float m2 = 0.f, m3 = 0.f, m4 = 0.f;
        #pragma unroll
        for (int i = 0; i < 8; i++) { m2 += b2[i]; m3 += b3[i]; m4 += b4[i]; }
        g_cw.b2[j] = dup2(b2[j] - m2 * 0.125f);
        g_cw.b3[j] = dup2(b3[j] - m3 * 0.125f);
        g_cw.b4[j] = dup2(b4[j] - m4 * 0.125f);
        g_cw.w5[j] = dup2(0.505f * w5[j]);
    }
    if (t == 80) {
        float wm = 0.f, bm = 0.f;
        #pragma unroll
        for (int i = 0; i < 8; i++) { wm += w1[i]; bm += b1[i]; }
        wm *= 0.125f; bm *= 0.125f;
        float A = 0.f, Bq = 0.f, Cq = 0.f;
        #pragma unroll
        for (int i = 0; i < 8; i++) {
            float u = w1[i] - wm, v = b1[i] - bm;
            A += u * u; Bq += u * v; Cq += v * v;
        }
        g_cw.A = dup2(A * (1.0f / 7.0f));
        g_cw.B = dup2(Bq * (2.0f / 7.0f));
        g_cw.C = dup2(Cq * (1.0f / 7.0f));
        g_cw.b5 = dup2(b5[0]);
    }
}

// ---------------- style MLP (one block per batch) ---------------------------
__global__ void style_k(const float* __restrict__ meta,
                        const float* __restrict__ mw1, const float* __restrict__ mb1,
                        const float* __restrict__ mw2, const float* __restrict__ mb2,
                        const float* __restrict__ mw3, const float* __restrict__ mb3,
                        const float* __restrict__ w1,  const float* __restrict__ b1)
{
#if __CUDA_ARCH__ >= 900
    cudaTriggerProgrammaticLaunchCompletion();
#endif
    __shared__ float sm[16], s1[64], s2[128], ss[64];
    int b = blockIdx.x, t = threadIdx.x;
    if (t < 16) sm[t] = meta[b * 16 + t];
    __syncthreads();
    if (t < 64) {
        float a = mb1[t];
        #pragma unroll
        for (int k = 0; k < 16; k++) a += sm[k] * mw1[k * 64 + t];
        s1[t] = fmaxf(a, 0.0f);
    }
    __syncthreads();
    {
        float a = mb2[t];
        #pragma unroll 16
        for (int k = 0; k < 64; k++) a += s1[k] * mw2[k * 128 + t];
        s2[t] = fmaxf(a, 0.0f);
    }
    __syncthreads();
    if (t < 64) {
        float a = mb3[t];
        #pragma unroll 16
        for (int k = 0; k < 128; k++) a += s2[k] * mw3[k * 64 + t];
        ss[t] = a;
    }
    __syncthreads();
    if (t < 8) {
        int j = t;
        float wm = 0.f, bm = 0.f;
        #pragma unroll
        for (int i = 0; i < 8; i++) { wm += w1[i]; bm += b1[i]; }
        wm *= 0.125f; bm *= 0.125f;
        float u = w1[j] - wm, v = b1[j] - bm;
        float* st = g_style + b * 72;
        float sc1 = ss[2 * j], bi1 = ss[2 * j + 1];
        st[j]      = sc1 * u;
        st[8 + j]  = sc1 * v;
        st[16 + j] = bi1;
        st[24 + j] = ss[16 + 2 * j] * SQRT7; st[32 + j] = ss[16 + 2 * j + 1];
        st[40 + j] = ss[32 + 2 * j] * SQRT7; st[48 + j] = ss[32 + 2 * j + 1];
        st[56 + j] = ss[48 + 2 * j] * SQRT7; st[64 + j] = ss[48 + 2 * j + 1];
    }
}

// ---------------- mid layer: const-weight matmul + AdaIN + folded lrelu -----
__device__ __forceinline__ void mid_layer(u64 h[PAIRS][8],
                                          const u64* __restrict__ w,
                                          const u64* __restrict__ bias,
                                          const u64* __restrict__ sab,
                                          u64 c98)
{
    u64 acc[PAIRS][8];
    #pragma unroll
    for (int j = 0; j < 8; j++) {
        u64 bj = bias[j];
        #pragma unroll
        for (int p = 0; p < PAIRS; p++) acc[p][j] = bj;
    }
    #pragma unroll
    for (int k = 0; k < 8; k++) {
        #pragma unroll
        for (int j = 0; j < 8; j++) {
            u64 wv = w[k * 8 + j];              // constant bank -> LDCU/UR
            #pragma unroll
            for (int p = 0; p < PAIRS; p++)
                acc[p][j] = fma2(h[p][k], wv, acc[p][j]);
        }
    }
    #pragma unroll
    for (int p = 0; p < PAIRS; p++) {
        u64 sa = mul2(acc[p][0], acc[p][0]);
        u64 sb = mul2(acc[p][4], acc[p][4]);
        #pragma unroll
        for (int j = 1; j < 4; j++) {
            sa = fma2(acc[p][j], acc[p][j], sa);
            sb = fma2(acc[p][j + 4], acc[p][j + 4], sb);
        }
        u64 s2 = add2(sa, sb);
        float v0, v1; up2(s2, v0, v1);
        u64 inv = pk2(rsqrt_ap(v0), rsqrt_ap(v1));
        #pragma unroll
        for (int j = 0; j < 8; j++) {
            u64 sc, bi; lds2(sab + 2 * j, sc, bi);
            u64 cn = mul2(acc[p][j], inv);
            h[p][j] = lrelu2f(fma2(sc, cn, bi), c98);
        }
    }
}

// ---------------- main pointwise kernel ----------------
__global__ __launch_bounds__(NTHR, 3)
void main_k(const float* __restrict__ x, float* __restrict__ out)
{
    __shared__ __align__(16) u64 spq1[16], sb1[8];
    __shared__ __align__(16) u64 sab0[16], sab1[16], sab2[16];

    int tid = threadIdx.x;
    int b = blockIdx.y;

    size_t base = (size_t)b * T_SZ + (size_t)blockIdx.x * ELEMS_PER_BLOCK + tid * (PAIRS * 2);
    const float4 xa = *reinterpret_cast<const float4*>(x + base);
    u64 xp[PAIRS] = { pk2(xa.x, xa.y), pk2(xa.z, xa.w) };

#if __CUDA_ARCH__ >= 900
    cudaGridDependencySynchronize();   // wait for both prologue branches
#endif
    if (tid < 8) {
        int j = tid;
        const float* st = g_style + b * 72;
        spq1[2 * j]     = dup2(st[j]);
        spq1[2 * j + 1] = dup2(st[8 + j]);
        sb1[j]          = dup2(st[16 + j]);
        sab0[2 * j] = dup2(st[24 + j]); sab0[2 * j + 1] = dup2(st[32 + j]);
        sab1[2 * j] = dup2(st[40 + j]); sab1[2 * j + 1] = dup2(st[48 + j]);
        sab2[2 * j] = dup2(st[56 + j]); sab2[2 * j + 1] = dup2(st[64 + j]);
    }
    __syncthreads();

    const u64 c98 = dup2(C98);

    u64 h[PAIRS][8];
    u64 rA = c_cw.A, rB = c_cw.B, rC = c_cw.C;
    // layer 1 + adain1 collapsed: var = quadratic in x (already /7)
    #pragma unroll
    for (int p = 0; p < PAIRS; p++) {
        u64 var = fma2(rA, mul2(xp[p], xp[p]), fma2(rB, xp[p], rC));
        float v0, v1; up2(var, v0, v1);
        u64 inv = pk2(rsqrt_ap(fmaxf(v0, 0.0f)), rsqrt_ap(fmaxf(v1, 0.0f)));
        #pragma unroll
        for (int j = 0; j < 8; j += 2) {
            u64 p0, q0v; lds2(spq1 + 2 * j, p0, q0v);
            u64 p1v, q1v; lds2(spq1 + 2 * j + 2, p1v, q1v);
            u64 bb0, bb1; lds2(sb1 + j, bb0, bb1);
            h[p][j]     = lrelu2f(fma2(fma2(p0, xp[p], q0v), inv, bb0), c98);
            h[p][j + 1] = lrelu2f(fma2(fma2(p1v, xp[p], q1v), inv, bb1), c98);
        }
    }

    mid_layer(h, c_cw.w2, c_cw.b2, sab0, c98);
    mid_layer(h, c_cw.w3, c_cw.b3, sab1, c98);
    mid_layer(h, c_cw.w4, c_cw.b4, sab2, c98);

    const u64 c505 = dup2(0.505f), c495 = dup2(0.495f);
    u64 o[PAIRS];
    u64 rb5 = c_cw.b5;
    #pragma unroll
    for (int p = 0; p < PAIRS; p++) {
        u64 acc = rb5;
        #pragma unroll
        for (int k = 0; k < 8; k++) acc = fma2(h[p][k], c_cw.w5[k], acc);
        o[p] = lrelu2(acc, c505, c495);
    }
    float a0, a1, a2, a3;
    up2(o[0], a0, a1); up2(o[1], a2, a3);
    *reinterpret_cast<float4*>(out + base) = make_float4(a0, a1, a2, a3);
}

extern "C" void kernel_launch(void* const* d_in, const int* in_sizes, int n_in,
                              void* d_out, int out_size)
{
    const float* x    = (const float*)d_in[0];
    const float* meta = (const float*)d_in[1];
    const float* mw1  = (const float*)d_in[2];
    const float* mb1  = (const float*)d_in[3];
    const float* mw2  = (const float*)d_in[4];
    const float* mb2  = (const float*)d_in[5];
    const float* mw3  = (const float*)d_in[6];
    const float* mb3  = (const float*)d_in[7];
    const float* w1   = (const float*)d_in[8];
    const float* b1   = (const float*)d_in[9];
    const float* w2   = (const float*)d_in[10];
    const float* b2   = (const float*)d_in[11];
    const float* w3   = (const float*)d_in[12];
    const float* b3   = (const float*)d_in[13];
    const float* w4   = (const float*)d_in[14];
    const float* b4   = (const float*)d_in[15];
    const float* w5   = (const float*)d_in[16];
    const float* b5   = (const float*)d_in[17];
    float* out = (float*)d_out;

    // Fork-join prologue DAG:
    //   branch A (side stream): wtrans_k -> memcpy(c_cw)
    //   branch B (stream 0):    style_k
    //   join -> main_k
    // Streams/events are host-side objects (no device allocation). Created per
    // call and intentionally not destroyed during capture.
    cudaStream_t s1;
    cudaStreamCreateWithFlags(&s1, cudaStreamNonBlocking);
    cudaEvent_t e_fork, e_join;
    cudaEventCreateWithFlags(&e_fork, cudaEventDisableTiming);
    cudaEventCreateWithFlags(&e_join, cudaEventDisableTiming);

    cudaEventRecord(e_fork, 0);
    cudaStreamWaitEvent(s1, e_fork, 0);

    // branch A
    wtrans_k<<<1, 128, 0, s1>>>(w1, b1, w2, b2, w3, b3, w4, b4, w5, b5);
    void *src = nullptr, *dst = nullptr;
    cudaGetSymbolAddress(&src, g_cw);
    cudaGetSymbolAddress(&dst, c_cw);
    cudaMemcpyAsync(dst, src, sizeof(CW), cudaMemcpyDeviceToDevice, s1);
    cudaEventRecord(e_join, s1);

    // branch B
    style_k<<<B_SZ, 128>>>(meta, mw1, mb1, mw2, mb2, mw3, mb3, w1, b1);

    // join
    cudaStreamWaitEvent(0, e_join, 0);

    // main kernel (PDL lets it launch early; gridsync covers both branches)
    cudaLaunchConfig_t cfg = {};
    cfg.gridDim = dim3(T_SZ / ELEMS_PER_BLOCK, B_SZ);
    cfg.blockDim = dim3(NTHR);
    cfg.dynamicSmemBytes = 0;
    cfg.stream = 0;
    cudaLaunchAttribute attrs[1];
    attrs[0].id = cudaLaunchAttributeProgrammaticStreamSerialization;
    attrs[0].val.programmaticStreamSerializationAllowed = 1;
    cfg.attrs = attrs;
    cfg.numAttrs = 1;
    cudaLaunchKernelEx(&cfg, main_k, x, out);
}

// round 11
// speedup vs baseline: 1.1434x; 1.1434x over previous
#include <cuda_runtime.h>
#include <cstdint>

typedef unsigned long long u64;

#define B_SZ 256
#define T_SZ 8192
#define PAIRS 2
#define NTHR 256
#define ELEMS_PER_BLOCK (NTHR * PAIRS * 2)   // 1024
#define SQRT7 2.6457513110645906f

// Per-batch folded style constants (mid-layer scales pre-multiplied by sqrt(7)):
// [0:8) p1  [8:16) q1  [16:24) bias1
// [24:32) scale2' [32:40) bias2 ... [56:64) scale4' [64:72) bias4
__device__ float g_style[B_SZ * 72];

// Grid-uniform transformed weights (centered, 0.505-prescaled, f32x2-dup'd).
// Lives in the constant bank; style_k block 0 writes it through the global
// alias (cudaGetSymbolAddress) — constant cache is invalidated per launch, so
// main_k's LDCU reads see the fresh values. No memcpy node needed.
struct CW {
    u64 w2[64], w3[64], w4[64];
    u64 b2[8],  b3[8],  b4[8];
    u64 w5[8];
    u64 A, B, C, b5;
};
__constant__ CW c_cw;

// ---------------- packed f32x2 helpers ----------------
__device__ __forceinline__ u64 pk2(float lo, float hi) {
    u64 r;
    asm("mov.b64 %0, {%1, %2};" : "=l"(r)
        : "r"(__float_as_uint(lo)), "r"(__float_as_uint(hi)));
    return r;
}
__device__ __forceinline__ void up2(u64 v, float& lo, float& hi) {
    unsigned a, b;
    asm("mov.b64 {%0, %1}, %2;" : "=r"(a), "=r"(b) : "l"(v));
    lo = __uint_as_float(a); hi = __uint_as_float(b);
}
__device__ __forceinline__ u64 dup2(float v) { return pk2(v, v); }
__device__ __forceinline__ u64 fma2(u64 a, u64 b, u64 c) {
    u64 d; asm("fma.rn.f32x2 %0, %1, %2, %3;" : "=l"(d) : "l"(a), "l"(b), "l"(c));
    return d;
}
__device__ __forceinline__ u64 mul2(u64 a, u64 b) {
    u64 d; asm("mul.rn.f32x2 %0, %1, %2;" : "=l"(d) : "l"(a), "l"(b));
    return d;
}
__device__ __forceinline__ u64 add2(u64 a, u64 b) {
    u64 d; asm("add.rn.f32x2 %0, %1, %2;" : "=l"(d) : "l"(a), "l"(b));
    return d;
}
__device__ __forceinline__ void lds2(const u64* p, u64& a, u64& b) {
    asm("ld.shared.v2.u64 {%0, %1}, [%2];"
        : "=l"(a), "=l"(b) : "l"(__cvta_generic_to_shared(p)));
}
__device__ __forceinline__ float rsqrt_ap(float v) {
    float r; asm("rsqrt.approx.f32 %0, %1;" : "=f"(r) : "f"(v));
    return r;
}

// folded lrelu feeding a 0.505-prescaled next layer
#define C98 0.980198019801980198f
__device__ __forceinline__ u64 lrelu2f(u64 v, u64 c98) {
    u64 a = v & 0x7fffffff7fffffffULL;
    return fma2(c98, a, v);
}
// full lrelu (output only)
__device__ __forceinline__ u64 lrelu2(u64 v, u64 c505, u64 c495) {
    u64 a = v & 0x7fffffff7fffffffULL;
    return fma2(c495, a, mul2(c505, v));
}

// ---------------- style MLP + weight transform (one block per batch) --------
__global__ void style_k(const float* __restrict__ meta,
                        const float* __restrict__ mw1, const float* __restrict__ mb1,
                        const float* __restrict__ mw2, const float* __restrict__ mb2,
                        const float* __restrict__ mw3, const float* __restrict__ mb3,
                        const float* __restrict__ w1,  const float* __restrict__ b1,
                        const float* __restrict__ w2,  const float* __restrict__ b2,
                        const float* __restrict__ w3,  const float* __restrict__ b3,
                        const float* __restrict__ w4,  const float* __restrict__ b4,
                        const float* __restrict__ w5,  const float* __restrict__ b5,
                        CW* __restrict__ cw)
{
#if __CUDA_ARCH__ >= 900
    cudaTriggerProgrammaticLaunchCompletion();
#endif
    __shared__ float sm[16], s1[64], s2[128], ss[64];
    int b = blockIdx.x, t = threadIdx.x;

    // Block 0: weight transform, written directly into the constant bank alias.
    if (b == 0) {
        if (t < 64) {
            float v2 = w2[t], v3 = w3[t], v4 = w4[t];
            float m2 = v2, m3 = v3, m4 = v4;
            #pragma unroll
            for (int d = 1; d < 8; d <<= 1) {
                m2 += __shfl_xor_sync(0xffffffffu, m2, d);
                m3 += __shfl_xor_sync(0xffffffffu, m3, d);
                m4 += __shfl_xor_sync(0xffffffffu, m4, d);
            }
            cw->w2[t] = dup2(0.505f * (v2 - m2 * 0.125f));
            cw->w3[t] = dup2(0.505f * (v3 - m3 * 0.125f));
            cw->w4[t] = dup2(0.505f * (v4 - m4 * 0.125f));
        }
        if (t >= 64 && t < 72) {
            int j = t - 64;
            float m2 = 0.f, m3 = 0.f, m4 = 0.f;
            #pragma unroll
            for (int i = 0; i < 8; i++) { m2 += b2[i]; m3 += b3[i]; m4 += b4[i]; }
            cw->b2[j] = dup2(b2[j] - m2 * 0.125f);
            cw->b3[j] = dup2(b3[j] - m3 * 0.125f);
            cw->b4[j] = dup2(b4[j] - m4 * 0.125f);
            cw->w5[j] = dup2(0.505f * w5[j]);
        }
        if (t == 80) {
            float wm = 0.f, bm = 0.f;
            #pragma unroll
            for (int i = 0; i < 8; i++) { wm += w1[i]; bm += b1[i]; }
            wm *= 0.125f; bm *= 0.125f;
            float A = 0.f, Bq = 0.f, Cq = 0.f;
            #pragma unroll
            for (int i = 0; i < 8; i++) {
                float u = w1[i] - wm, v = b1[i] - bm;
                A += u * u; Bq += u * v; Cq += v * v;
            }
            cw->A = dup2(A * (1.0f / 7.0f));
            cw->B = dup2(Bq * (2.0f / 7.0f));
            cw->C = dup2(Cq * (1.0f / 7.0f));
            cw->b5 = dup2(b5[0]);
        }
    }

    if (t < 16) sm[t] = meta[b * 16 + t];
    __syncthreads();
    if (t < 64) {
        float a = mb1[t];
        #pragma unroll
        for (int k = 0; k < 16; k++) a += sm[k] * mw1[k * 64 + t];
        s1[t] = fmaxf(a, 0.0f);
    }
    __syncthreads();
    {
        float a = mb2[t];
        #pragma unroll 16
        for (int k = 0; k < 64; k++) a += s1[k] * mw2[k * 128 + t];
        s2[t] = fmaxf(a, 0.0f);
    }
    __syncthreads();
    if (t < 64) {
        float a = mb3[t];
        #pragma unroll 16
        for (int k = 0; k < 128; k++) a += s2[k] * mw3[k * 64 + t];
        ss[t] = a;
    }
    __syncthreads();
    if (t < 8) {
        int j = t;
        float wm = 0.f, bm = 0.f;
        #pragma unroll
        for (int i = 0; i < 8; i++) { wm += w1[i]; bm += b1[i]; }
        wm *= 0.125f; bm *= 0.125f;
        float u = w1[j] - wm, v = b1[j] - bm;
        float* st = g_style + b * 72;
        float sc1 = ss[2 * j], bi1 = ss[2 * j + 1];
        st[j]      = sc1 * u;
        st[8 + j]  = sc1 * v;
        st[16 + j] = bi1;
        st[24 + j] = ss[16 + 2 * j] * SQRT7; st[32 + j] = ss[16 + 2 * j + 1];
        st[40 + j] = ss[32 + 2 * j] * SQRT7; st[48 + j] = ss[32 + 2 * j + 1];
        st[56 + j] = ss[48 + 2 * j] * SQRT7; st[64 + j] = ss[48 + 2 * j + 1];
    }
}

// ---------------- mid layer: const-weight matmul + AdaIN + folded lrelu -----
__device__ __forceinline__ void mid_layer(u64 h[PAIRS][8],
                                          const u64* __restrict__ w,
                                          const u64* __restrict__ bias,
                                          const u64* __restrict__ sab,
                                          u64 c98)
{
    u64 acc[PAIRS][8];
    #pragma unroll
    for (int j = 0; j < 8; j++) {
        u64 bj = bias[j];
        #pragma unroll
        for (int p = 0; p < PAIRS; p++) acc[p][j] = bj;
    }
    #pragma unroll
    for (int k = 0; k < 8; k++) {
        #pragma unroll
        for (int j = 0; j < 8; j++) {
            u64 wv = w[k * 8 + j];              // constant bank -> LDCU/UR
            #pragma unroll
            for (int p = 0; p < PAIRS; p++)
                acc[p][j] = fma2(h[p][k], wv, acc[p][j]);
        }
    }
    // compute both pairs' inv first, then one style load per j serves both
    u64 inv[PAIRS];
    #pragma unroll
    for (int p = 0; p < PAIRS; p++) {
        u64 sa = mul2(acc[p][0], acc[p][0]);
        u64 sb = mul2(acc[p][4], acc[p][4]);
        #pragma unroll
        for (int j = 1; j < 4; j++) {
            sa = fma2(acc[p][j], acc[p][j], sa);
            sb = fma2(acc[p][j + 4], acc[p][j + 4], sb);
        }
        u64 s2 = add2(sa, sb);
        float v0, v1; up2(s2, v0, v1);
        inv[p] = pk2(rsqrt_ap(v0), rsqrt_ap(v1));
    }
    #pragma unroll
    for (int j = 0; j < 8; j++) {
        u64 sc, bi; lds2(sab + 2 * j, sc, bi);  // one LDS.128 for both pairs
        #pragma unroll
        for (int p = 0; p < PAIRS; p++) {
            u64 cn = mul2(acc[p][j], inv[p]);
            h[p][j] = lrelu2f(fma2(sc, cn, bi), c98);
        }
    }
}

// ---------------- main pointwise kernel ----------------
__global__ __launch_bounds__(NTHR, 3)
void main_k(const float* __restrict__ x, float* __restrict__ out)
{
    __shared__ __align__(16) u64 spq1[16], sb1[8];
    __shared__ __align__(16) u64 sab0[16], sab1[16], sab2[16];

    int tid = threadIdx.x;
    int b = blockIdx.y;

    size_t base = (size_t)b * T_SZ + (size_t)blockIdx.x * ELEMS_PER_BLOCK + tid * (PAIRS * 2);
    const float4 xa = *reinterpret_cast<const float4*>(x + base);
    u64 xp[PAIRS] = { pk2(xa.x, xa.y), pk2(xa.z, xa.w) };

#if __CUDA_ARCH__ >= 900
    cudaGridDependencySynchronize();   // wait for style_k completion (PDL)
#endif
    if (tid < 8) {
        int j = tid;
        const float* st = g_style + b * 72;
        spq1[2 * j]     = dup2(st[j]);
        spq1[2 * j + 1] = dup2(st[8 + j]);
        sb1[j]          = dup2(st[16 + j]);
        sab0[2 * j] = dup2(st[24 + j]); sab0[2 * j + 1] = dup2(st[32 + j]);
        sab1[2 * j] = dup2(st[40 + j]); sab1[2 * j + 1] = dup2(st[48 + j]);
        sab2[2 * j] = dup2(st[56 + j]); sab2[2 * j + 1] = dup2(st[64 + j]);
    }
    __syncthreads();

    const u64 c98 = dup2(C98);

    u64 h[PAIRS][8];
    u64 rA = c_cw.A, rB = c_cw.B, rC = c_cw.C;
    // layer 1 + adain1 collapsed: var = quadratic in x (already /7)
    u64 inv1[PAIRS];
    #pragma unroll
    for (int p = 0; p < PAIRS; p++) {
        u64 var = fma2(rA, mul2(xp[p], xp[p]), fma2(rB, xp[p], rC));
        float v0, v1; up2(var, v0, v1);
        inv1[p] = pk2(rsqrt_ap(fmaxf(v0, 0.0f)), rsqrt_ap(fmaxf(v1, 0.0f)));
    }
    #pragma unroll
    for (int j = 0; j < 8; j += 2) {
        u64 p0, q0v; lds2(spq1 + 2 * j, p0, q0v);
        u64 p1v, q1v; lds2(spq1 + 2 * j + 2, p1v, q1v);
        u64 bb0, bb1; lds2(sb1 + j, bb0, bb1);
        #pragma unroll
        for (int p = 0; p < PAIRS; p++) {
            h[p][j]     = lrelu2f(fma2(fma2(p0, xp[p], q0v), inv1[p], bb0), c98);
            h[p][j + 1] = lrelu2f(fma2(fma2(p1v, xp[p], q1v), inv1[p], bb1), c98);
        }
    }

    mid_layer(h, c_cw.w2, c_cw.b2, sab0, c98);
    mid_layer(h, c_cw.w3, c_cw.b3, sab1, c98);
    mid_layer(h, c_cw.w4, c_cw.b4, sab2, c98);

    const u64 c505 = dup2(0.505f), c495 = dup2(0.495f);
    u64 o[PAIRS];
    u64 rb5 = c_cw.b5;
    #pragma unroll
    for (int p = 0; p < PAIRS; p++) {
        u64 acc = rb5;
        #pragma unroll
        for (int k = 0; k < 8; k++) acc = fma2(h[p][k], c_cw.w5[k], acc);
        o[p] = lrelu2(acc, c505, c495);
    }
    float a0, a1, a2, a3;
    up2(o[0], a0, a1); up2(o[1], a2, a3);
    *reinterpret_cast<float4*>(out + base) = make_float4(a0, a1, a2, a3);
}

extern "C" void kernel_launch(void* const* d_in, const int* in_sizes, int n_in,
                              void* d_out, int out_size)
{
    const float* x    = (const float*)d_in[0];
    const float* meta = (const float*)d_in[1];
    const float* mw1  = (const float*)d_in[2];
    const float* mb1  = (const float*)d_in[3];
    const float* mw2  = (const float*)d_in[4];
    const float* mb2  = (const float*)d_in[5];
    const float* mw3  = (const float*)d_in[6];
    const float* mb3  = (const float*)d_in[7];
    const float* w1   = (const float*)d_in[8];
    const float* b1   = (const float*)d_in[9];
    const float* w2   = (const float*)d_in[10];
    const float* b2   = (const float*)d_in[11];
    const float* w3   = (const float*)d_in[12];
    const float* b3   = (const float*)d_in[13];
    const float* w4   = (const float*)d_in[14];
    const float* b4   = (const float*)d_in[15];
    const float* w5   = (const float*)d_in[16];
    const float* b5   = (const float*)d_in[17];
    float* out = (float*)d_out;

    // Device-global alias of the constant bank; style_k block 0 writes it.
    void* cw_alias = nullptr;
    cudaGetSymbolAddress(&cw_alias, c_cw);

    // Node 1: style MLP + weight transform
    style_k<<<B_SZ, 128>>>(meta, mw1, mb1, mw2, mb2, mw3, mb3, w1, b1,
                           w2, b2, w3, b3, w4, b4, w5, b5, (CW*)cw_alias);

    // Node 2: main kernel with PDL against style_k
    cudaLaunchConfig_t cfg = {};
    cfg.gridDim = dim3(T_SZ / ELEMS_PER_BLOCK, B_SZ);
    cfg.blockDim = dim3(NTHR);
    cfg.dynamicSmemBytes = 0;
    cfg.stream = 0;
    cudaLaunchAttribute attrs[1];
    attrs[0].id = cudaLaunchAttributeProgrammaticStreamSerialization;
    attrs[0].val.programmaticStreamSerializationAllowed = 1;
    cfg.attrs = attrs;
    cfg.numAttrs = 1;
    cudaLaunchKernelEx(&cfg, main_k, x, out);
}